// round 9
// baseline (speedup 1.0000x reference)
#include <cuda_runtime.h>

// out[s,:] = W_tok[x[s],:] + b_tok + W_pos[(S-1)-s,:] + b_pos
// S=8192, D=1024 fp32.
// R8: persistent single-wave (R7 win) + higher residency. 8 CTAs/SM
// (grid 1184 = 148x8, one wave, 64 warps/SM) requires <=32 regs/thread:
// pointer-increment indexing replaces per-iter 64-bit address math.

constexpr int SEQ   = 8192;
constexpr int EMBED = 1024;
constexpr int VEC   = EMBED / 4;   // 256 float4 per row
constexpr int CTAS_PER_SM = 8;
constexpr int GRID  = 148 * CTAS_PER_SM;   // 1184, exactly one wave

__global__ __launch_bounds__(256, CTAS_PER_SM)
void linear_embedding_kernel(const int* __restrict__ x,
                             const float4* __restrict__ W_tok,
                             const float4* __restrict__ b_tok,
                             const float4* __restrict__ W_pos,
                             const float4* __restrict__ b_pos,
                             float4* __restrict__ out)
{
    const int t      = threadIdx.x;
    const int stride = GRID;

    // Bias for this thread's column (zeros in practice; L2-resident).
    const float4 bt = __ldg(&b_tok[t]);
    const float4 bp = __ldg(&b_pos[t]);
    float4 b;
    b.x = bt.x + bp.x; b.y = bt.y + bp.y;
    b.z = bt.z + bp.z; b.w = bt.w + bp.w;

    int s = blockIdx.x;

    // Walking pointers (avoid per-iter 64-bit index math -> fewer regs).
    const float4* wtok_t = W_tok + t;                               // + tok*VEC per use
    const float4* wpos   = W_pos + (long long)(SEQ - 1 - s) * VEC + t;  // -= stride*VEC
    float4*       o      = out   + (long long)s * VEC + t;              // += stride*VEC
    const int*    xp     = x + s;                                       // += stride

    // Prologue: tokens 2 stages ahead, rows 1 stage ahead.
    int tok0 = __ldg(xp);
    int tok1 = (s + stride < SEQ) ? __ldg(xp + stride) : 0;

    float4 a0 = __ldg(wtok_t + (long long)tok0 * VEC);
    float4 p0 = __ldg(wpos);

    while (true) {
        const int s_next = s + stride;
        const bool more  = (s_next < SEQ);

        float4 a1, p1;
        if (more) {
            // Prefetch next row + token id 2 stages ahead.
            a1 = __ldg(wtok_t + (long long)tok1 * VEC);
            p1 = __ldg(wpos - stride * VEC);
            tok1 = (s_next + stride < SEQ) ? __ldg(xp + 2 * stride) : 0;
        }

        // Consume current row.
        float4 r;
        r.x = (a0.x + p0.x) + b.x;
        r.y = (a0.y + p0.y) + b.y;
        r.z = (a0.z + p0.z) + b.z;
        r.w = (a0.w + p0.w) + b.w;
        *o = r;

        if (!more) break;

        // Rotate.
        s = s_next;
        a0 = a1; p0 = p1;
        wpos -= stride * VEC;
        o    += stride * VEC;
        xp   += stride;
    }
}

extern "C" void kernel_launch(void* const* d_in, const int* in_sizes, int n_in,
                              void* d_out, int out_size)
{
    const int*    x     = (const int*)d_in[0];
    const float4* W_tok = (const float4*)d_in[1];
    const float4* b_tok = (const float4*)d_in[2];
    const float4* W_pos = (const float4*)d_in[3];
    const float4* b_pos = (const float4*)d_in[4];
    float4* out = (float4*)d_out;

    linear_embedding_kernel<<<GRID, 256>>>(x, W_tok, b_tok, W_pos, b_pos, out);
}